// round 16
// baseline (speedup 1.0000x reference)
#include <cuda_runtime.h>
#include <cuda_fp16.h>
#include <cstdint>

#define NN 40000
#define EE 640000
#define BB 256

// ---------------- scratch (device globals; no allocation) ----------------
__device__ __half g_yl[NN * 128];      // lin_l output (gathered) fp16
__device__ __half g_yr[NN * 128];      // lin_r output fp16
__device__ __half g_h1[NN * 128];      // layer-1 output fp16
__device__ float g_h2[NN * 128];       // layer-2 output fp32 (s2s input)
__device__ float g_inv[NN];
__device__ int   g_dc[2 * NN];         // deg | cursor
__device__ int   g_start[NN + 1];
__device__ int   g_csr[EE];            // src ids sorted by dst
__device__ int   g_seg[BB + 1];
__device__ __half g_Wch[512 * 256];    // fp16 [Wih[:,:128]+Whh | Wih[:,128:]]
__device__ float g_bl[512];            // bih + bhh
__device__ float g_s1[128], g_t1[128], g_s2[128], g_t2[128];

// ---------------- helpers ----------------
__device__ __forceinline__ float sigmoidf_(float x) { return 1.f / (1.f + expf(-x)); }

__device__ __forceinline__ void mma_f16(float c[4], uint32_t a0, uint32_t a1,
                                        uint32_t a2, uint32_t a3,
                                        uint32_t b0, uint32_t b1) {
    asm volatile(
        "mma.sync.aligned.m16n8k16.row.col.f32.f16.f16.f32 "
        "{%0,%1,%2,%3}, {%4,%5,%6,%7}, {%8,%9}, {%0,%1,%2,%3};\n"
        : "+f"(c[0]), "+f"(c[1]), "+f"(c[2]), "+f"(c[3])
        : "r"(a0), "r"(a1), "r"(a2), "r"(a3), "r"(b0), "r"(b1));
}

__device__ __forceinline__ float dot8(float4 w0, float4 w1, float4 v0, float4 v1) {
    return w0.x * v0.x + w0.y * v0.y + w0.z * v0.z + w0.w * v0.w
         + w1.x * v1.x + w1.y * v1.y + w1.z * v1.z + w1.w * v1.w;
}

__device__ __forceinline__ float dot8h(uint4 wq, float4 v0, float4 v1) {
    float2 f0 = __half22float2(*(__half2*)&wq.x);
    float2 f1 = __half22float2(*(__half2*)&wq.y);
    float2 f2 = __half22float2(*(__half2*)&wq.z);
    float2 f3 = __half22float2(*(__half2*)&wq.w);
    return f0.x * v0.x + f0.y * v0.y + f1.x * v0.z + f1.y * v0.w
         + f2.x * v1.x + f2.y * v1.y + f3.x * v1.z + f3.y * v1.w;
}

__device__ __forceinline__ void acc8(float4& a0, float4& a1, uint4 u) {
    float2 f0 = __half22float2(*(__half2*)&u.x);
    float2 f1 = __half22float2(*(__half2*)&u.y);
    float2 f2 = __half22float2(*(__half2*)&u.z);
    float2 f3 = __half22float2(*(__half2*)&u.w);
    a0.x += f0.x; a0.y += f0.y; a0.z += f1.x; a0.w += f1.y;
    a1.x += f2.x; a1.y += f2.y; a1.z += f3.x; a1.w += f3.y;
}

// smem A-tile loaders: fp32 source (convert) vs fp16 source (raw copy)
__device__ __forceinline__ void load_a4(__half* dst, const float* src) {
    float4 v = *(const float4*)src;
    *(__half2*)dst       = __floats2half2_rn(v.x, v.y);
    *(__half2*)(dst + 2) = __floats2half2_rn(v.z, v.w);
}
__device__ __forceinline__ void load_a4(__half* dst, const __half* src) {
    *(uint2*)dst = *(const uint2*)src;
}

// ---------------- fused prep: pack Wch/bl, fold BN, zero counters, seg bounds ----------------
__global__ void k_prep(const float* __restrict__ Wih, const float* __restrict__ Whh,
                       const float* __restrict__ bih, const float* __restrict__ bhh,
                       const float* __restrict__ g1, const float* __restrict__ be1,
                       const float* __restrict__ rm1, const float* __restrict__ rv1,
                       const float* __restrict__ b1l,
                       const float* __restrict__ g2, const float* __restrict__ be2,
                       const float* __restrict__ rm2, const float* __restrict__ rv2,
                       const float* __restrict__ b2l,
                       const int* __restrict__ batch) {
    int i = blockIdx.x * blockDim.x + threadIdx.x;
    if (i < 512 * 256) {
        int r = i >> 8, k = i & 255;
        float w = Wih[r * 256 + k];
        if (k < 128) w += Whh[r * 128 + k];
        g_Wch[i] = __float2half(w);
    }
    if (i < 512) g_bl[i] = bih[i] + bhh[i];
    if (i < 128) {
        float s = g1[i] * rsqrtf(rv1[i] + 1e-5f);
        g_s1[i] = s; g_t1[i] = be1[i] + (b1l[i] - rm1[i]) * s;
    } else if (i < 256) {
        int j = i - 128;
        float s = g2[j] * rsqrtf(rv2[j] + 1e-5f);
        g_s2[j] = s; g_t2[j] = be2[j] + (b2l[j] - rm2[j]) * s;
    }
    if (i < NN) {
        g_dc[i] = 0; g_dc[NN + i] = 0;
        int b = batch[i];
        int prev = (i == 0) ? -1 : batch[i - 1];
        for (int q = prev + 1; q <= b; q++) g_seg[q] = i;
        if (i == NN - 1)
            for (int q = b + 1; q <= BB; q++) g_seg[q] = NN;
    }
}

// ---------------- CSR build ----------------
__global__ void k_hist(const int* __restrict__ ei) {
    int e = blockIdx.x * blockDim.x + threadIdx.x;
    if (e < EE) atomicAdd(&g_dc[ei[EE + e]], 1);
}

__global__ void k_scan() {  // single block, 256 threads
    __shared__ int part[256];
    int tid = threadIdx.x;
    const int chunk = (NN + 255) / 256;
    int b0 = tid * chunk, b1 = min(b0 + chunk, NN);
    int s = 0;
    for (int i = b0; i < b1; i++) s += g_dc[i];
    part[tid] = s;
    __syncthreads();
    for (int off = 1; off < 256; off <<= 1) {
        int v = (tid >= off) ? part[tid - off] : 0;
        __syncthreads();
        part[tid] += v;
        __syncthreads();
    }
    int base = (tid == 0) ? 0 : part[tid - 1];
    for (int i = b0; i < b1; i++) {
        int d = g_dc[i];
        g_start[i] = base;
        g_inv[i] = 1.f / (float)max(d, 1);
        base += d;
    }
    if (tid == 255) g_start[NN] = base;
}

__global__ void k_fill(const int* __restrict__ ei) {
    int e = blockIdx.x * blockDim.x + threadIdx.x;
    if (e >= EE) return;
    int s = ei[e], d = ei[EE + e];
    int pos = g_start[d] + atomicAdd(&g_dc[NN + d], 1);
    g_csr[pos] = s;
}

// ---------------- fp16 tensor-core GEMM (unchanged from R15) ----------------
template <typename TA>
__global__ __launch_bounds__(256) void k_gemm_f16(
    const TA* __restrict__ A,
    const float* __restrict__ Wl, const float* __restrict__ Wr,
    __half* __restrict__ Yl, __half* __restrict__ Yr) {
    __shared__ __half As[128][40];
    __shared__ __half Bs[128][40];
    const float* W = blockIdx.y ? Wr : Wl;
    __half* Y = blockIdx.y ? Yr : Yl;
    int m0 = blockIdx.x * 128;
    int tid = threadIdx.x;
    int warp = tid >> 5, lane = tid & 31;
    int wm = warp >> 1, wn = warp & 1;
    int gid = lane >> 2, tig = lane & 3;

    float acc[2][8][4];
#pragma unroll
    for (int i = 0; i < 2; i++)
#pragma unroll
        for (int j = 0; j < 8; j++)
#pragma unroll
            for (int q = 0; q < 4; q++) acc[i][j][q] = 0.f;

    int lrow = tid >> 3;
    int lk4 = (tid & 7) * 4;

    for (int kc = 0; kc < 128; kc += 32) {
#pragma unroll
        for (int i = 0; i < 4; i++) {
            int row = lrow + 32 * i;
            int r = m0 + row;
            int rc = min(r, NN - 1);
            load_a4(&As[row][lk4], A + (size_t)rc * 128 + kc + lk4);
            float4 w = *(const float4*)(W + (size_t)row * 128 + kc + lk4);
            *(__half2*)&Bs[row][lk4]     = __floats2half2_rn(w.x, w.y);
            *(__half2*)&Bs[row][lk4 + 2] = __floats2half2_rn(w.z, w.w);
        }
        __syncthreads();
#pragma unroll
        for (int ks = 0; ks < 32; ks += 16) {
            uint32_t a[2][4];
#pragma unroll
            for (int mt = 0; mt < 2; mt++) {
                int mb = wm * 32 + mt * 16;
                a[mt][0] = *(const uint32_t*)&As[mb + gid][ks + tig * 2];
                a[mt][1] = *(const uint32_t*)&As[mb + gid + 8][ks + tig * 2];
                a[mt][2] = *(const uint32_t*)&As[mb + gid][ks + tig * 2 + 8];
                a[mt][3] = *(const uint32_t*)&As[mb + gid + 8][ks + tig * 2 + 8];
            }
#pragma unroll
            for (int nt = 0; nt < 8; nt++) {
                int nb = wn * 64 + nt * 8;
                uint32_t b0 = *(const uint32_t*)&Bs[nb + gid][ks + tig * 2];
                uint32_t b1 = *(const uint32_t*)&Bs[nb + gid][ks + tig * 2 + 8];
                mma_f16(acc[0][nt], a[0][0], a[0][1], a[0][2], a[0][3], b0, b1);
                mma_f16(acc[1][nt], a[1][0], a[1][1], a[1][2], a[1][3], b0, b1);
            }
        }
        __syncthreads();
    }

    int ncol0 = wn * 64;
#pragma unroll
    for (int mt = 0; mt < 2; mt++) {
        int row0 = m0 + wm * 32 + mt * 16 + gid;
        int row1 = row0 + 8;
#pragma unroll
        for (int nt = 0; nt < 8; nt++) {
            int c = ncol0 + nt * 8 + tig * 2;
            if (row0 < NN)
                *(__half2*)(Y + (size_t)row0 * 128 + c) =
                    __floats2half2_rn(acc[mt][nt][0], acc[mt][nt][1]);
            if (row1 < NN)
                *(__half2*)(Y + (size_t)row1 * 128 + c) =
                    __floats2half2_rn(acc[mt][nt][2], acc[mt][nt][3]);
        }
    }
}

// ---------------- CSR aggregation: half-warp-per-edge, uint4 gather ----------------
// warp per node; lane = (half, q): half in {0,1} processes edges e0+half, +2, ...;
// lane loads uint4 (8 halves = dims [8q, 8q+8)). Cross-half combine = 8 shfls/node.
template <int FP16OUT>
__device__ __forceinline__ void agg_body(const float* __restrict__ s,
                                         const float* __restrict__ t,
                                         float* __restrict__ out32,
                                         __half* __restrict__ out16) {
    int gt = blockIdx.x * blockDim.x + threadIdx.x;
    int w = gt >> 5;
    if (w >= NN) return;
    int lane = gt & 31;
    int half = lane >> 4;          // 0/1
    int q = lane & 15;             // 0..15 -> dims [8q, 8q+8)
    int e0 = g_start[w], e1 = g_start[w + 1];

    const uint4* Y4 = (const uint4*)g_yl;   // row = 16 uint4
    float4 a0 = make_float4(0.f, 0.f, 0.f, 0.f);
    float4 a1 = make_float4(0.f, 0.f, 0.f, 0.f);
    float4 b0 = make_float4(0.f, 0.f, 0.f, 0.f);
    float4 b1 = make_float4(0.f, 0.f, 0.f, 0.f);

    int e = e0 + half;
    for (; e + 2 < e1; e += 4) {
        int sa = __ldg(g_csr + e);
        int sb = __ldg(g_csr + e + 2);
        uint4 ua = Y4[(size_t)sa * 16 + q];
        uint4 ub = Y4[(size_t)sb * 16 + q];
        acc8(a0, a1, ua);
        acc8(b0, b1, ub);
    }
    for (; e < e1; e += 2) {
        int sa = __ldg(g_csr + e);
        uint4 ua = Y4[(size_t)sa * 16 + q];
        acc8(a0, a1, ua);
    }
    a0.x += b0.x; a0.y += b0.y; a0.z += b0.z; a0.w += b0.w;
    a1.x += b1.x; a1.y += b1.y; a1.z += b1.z; a1.w += b1.w;

    // cross-half combine (both halves end with the full sum)
    a0.x += __shfl_xor_sync(0xffffffffu, a0.x, 16);
    a0.y += __shfl_xor_sync(0xffffffffu, a0.y, 16);
    a0.z += __shfl_xor_sync(0xffffffffu, a0.z, 16);
    a0.w += __shfl_xor_sync(0xffffffffu, a0.w, 16);
    a1.x += __shfl_xor_sync(0xffffffffu, a1.x, 16);
    a1.y += __shfl_xor_sync(0xffffffffu, a1.y, 16);
    a1.z += __shfl_xor_sync(0xffffffffu, a1.z, 16);
    a1.w += __shfl_xor_sync(0xffffffffu, a1.w, 16);

    float iv = g_inv[w];
    uint4 ur = ((const uint4*)g_yr)[(size_t)w * 16 + q];
    float2 r0 = __half22float2(*(__half2*)&ur.x);
    float2 r1 = __half22float2(*(__half2*)&ur.y);
    float2 r2 = __half22float2(*(__half2*)&ur.z);
    float2 r3 = __half22float2(*(__half2*)&ur.w);
    const float4* S4 = (const float4*)s;
    const float4* T4 = (const float4*)t;
    float4 sv0 = S4[2 * q], sv1 = S4[2 * q + 1];
    float4 tv0 = T4[2 * q], tv1 = T4[2 * q + 1];

    float4 o0, o1;
    o0.x = fmaxf(fmaf(fmaf(a0.x, iv, r0.x), sv0.x, tv0.x), 0.f);
    o0.y = fmaxf(fmaf(fmaf(a0.y, iv, r0.y), sv0.y, tv0.y), 0.f);
    o0.z = fmaxf(fmaf(fmaf(a0.z, iv, r1.x), sv0.z, tv0.z), 0.f);
    o0.w = fmaxf(fmaf(fmaf(a0.w, iv, r1.y), sv0.w, tv0.w), 0.f);
    o1.x = fmaxf(fmaf(fmaf(a1.x, iv, r2.x), sv1.x, tv1.x), 0.f);
    o1.y = fmaxf(fmaf(fmaf(a1.y, iv, r2.y), sv1.y, tv1.y), 0.f);
    o1.z = fmaxf(fmaf(fmaf(a1.z, iv, r3.x), sv1.z, tv1.z), 0.f);
    o1.w = fmaxf(fmaf(fmaf(a1.w, iv, r3.y), sv1.w, tv1.w), 0.f);

    if (FP16OUT) {
        if (half == 0) {
            uint4 pk;
            *(__half2*)&pk.x = __floats2half2_rn(o0.x, o0.y);
            *(__half2*)&pk.y = __floats2half2_rn(o0.z, o0.w);
            *(__half2*)&pk.z = __floats2half2_rn(o1.x, o1.y);
            *(__half2*)&pk.w = __floats2half2_rn(o1.z, o1.w);
            ((uint4*)out16)[(size_t)w * 16 + q] = pk;
        }
    } else {
        // full warp writes 32 float4 = 128 floats (each lane writes its half's float4)
        float4 oh = half ? o1 : o0;
        ((float4*)out32)[(size_t)w * 32 + 2 * q + half] = oh;
    }
}

__global__ void k_agg_h(const float* __restrict__ s, const float* __restrict__ t,
                        __half* __restrict__ out) {
    agg_body<1>(s, t, nullptr, out);
}
__global__ void k_agg_f(const float* __restrict__ s, const float* __restrict__ t,
                        float* __restrict__ out) {
    agg_body<0>(s, t, out, nullptr);
}

// ---------------- fused set2set (3 steps) + final projection (unchanged) ----------------
__global__ __launch_bounds__(256) void k_s2s(const float* __restrict__ Wp,
                                             const float* __restrict__ bp,
                                             float* __restrict__ out) {
    int blk = blockIdx.x;
    int tid = threadIdx.x;
    int warp = tid >> 5, lane = tid & 31;
    int gr = warp >> 2;
    int wl = warp & 3;
    int g = blk * 2 + gr;

    __shared__ float sh_v[2][256];
    __shared__ float sh_q[2][128];
    __shared__ float sh_c[2][128];
    __shared__ float sh_gates[2][512];
    __shared__ float sh_r[2][4][128];
    __shared__ float sh_s[2][8];

    if (tid < 128) { sh_c[0][tid] = 0.f; sh_c[1][tid] = 0.f; }
    __syncthreads();

    int s0 = g_seg[g], s1 = g_seg[g + 1];
    const float4* H4 = (const float4*)g_h2;

    for (int step = 0; step < 3; step++) {
        if (step == 0) {
            float b0 = g_bl[tid], b1 = g_bl[256 + tid];
            sh_gates[0][tid] = b0; sh_gates[0][256 + tid] = b1;
            sh_gates[1][tid] = b0; sh_gates[1][256 + tid] = b1;
        } else {
            const float4* VA = (const float4*)sh_v[0];
            const float4* VB = (const float4*)sh_v[1];
            float4 va0 = VA[2 * lane], va1 = VA[2 * lane + 1];
            float4 vb0 = VB[2 * lane], vb1 = VB[2 * lane + 1];
#pragma unroll 4
            for (int j = 0; j < 64; j++) {
                int r = warp * 64 + j;
                uint4 wq = *(const uint4*)(g_Wch + (size_t)r * 256 + lane * 8);
                float pA = dot8h(wq, va0, va1);
                float pB = dot8h(wq, vb0, vb1);
#pragma unroll
                for (int o = 16; o > 0; o >>= 1) {
                    pA += __shfl_xor_sync(0xffffffffu, pA, o);
                    pB += __shfl_xor_sync(0xffffffffu, pB, o);
                }
                if (lane == 0) {
                    float bb = g_bl[r];
                    sh_gates[0][r] = pA + bb;
                    sh_gates[1][r] = pB + bb;
                }
            }
        }
        __syncthreads();

        {
            int gg = tid >> 7, d = tid & 127;
            float ig = sh_gates[gg][d], fg = sh_gates[gg][128 + d];
            float gv = sh_gates[gg][256 + d], og = sh_gates[gg][384 + d];
            float c0 = sh_c[gg][d];
            float cn = sigmoidf_(fg) * c0 + sigmoidf_(ig) * tanhf(gv);
            float hn = sigmoidf_(og) * tanhf(cn);
            sh_c[gg][d] = cn;
            sh_q[gg][d] = hn;
        }
        __syncthreads();

        float4 qv = ((const float4*)sh_q[gr])[lane];
        float wmax = -3.402823466e38f;
        for (int n = s0 + wl; n < s1; n += 4) {
            float4 hv = H4[(size_t)n * 32 + lane];
            float p = hv.x * qv.x + hv.y * qv.y + hv.z * qv.z + hv.w * qv.w;
#pragma unroll
            for (int o = 16; o > 0; o >>= 1) p += __shfl_xor_sync(0xffffffffu, p, o);
            wmax = fmaxf(wmax, p);
        }
        if (lane == 0) sh_s[gr][wl] = wmax;
        __syncthreads();
        float emax = fmaxf(fmaxf(sh_s[gr][0], sh_s[gr][1]),
                           fmaxf(sh_s[gr][2], sh_s[gr][3]));

        float asum = 0.f;
        float4 racc = make_float4(0.f, 0.f, 0.f, 0.f);
        for (int n = s0 + wl; n < s1; n += 4) {
            float4 hv = H4[(size_t)n * 32 + lane];
            float p = hv.x * qv.x + hv.y * qv.y + hv.z * qv.z + hv.w * qv.w;
#pragma unroll
            for (int o = 16; o > 0; o >>= 1) p += __shfl_xor_sync(0xffffffffu, p, o);
            float a = expf(p - emax);
            asum += a;
            racc.x += a * hv.x; racc.y += a * hv.y; racc.z += a * hv.z; racc.w += a * hv.w;
        }
        ((float4*)sh_r[gr][wl])[lane] = racc;
        if (lane == 0) sh_s[gr][4 + wl] = asum;
        __syncthreads();

        {
            int gg = tid >> 7, d = tid & 127;
            float den = sh_s[gg][4] + sh_s[gg][5] + sh_s[gg][6] + sh_s[gg][7];
            float rsum = sh_r[gg][0][d] + sh_r[gg][1][d] + sh_r[gg][2][d] + sh_r[gg][3][d];
            float r = (den > 0.f) ? rsum / den : 0.f;
            sh_v[gg][d] = sh_q[gg][d];
            sh_v[gg][128 + d] = r;
        }
        __syncthreads();
    }

    {
        const float4* VA = (const float4*)sh_v[0];
        const float4* VB = (const float4*)sh_v[1];
        float4 va0 = VA[lane], va1 = VA[32 + lane];
        float4 vb0 = VB[lane], vb1 = VB[32 + lane];
#pragma unroll 4
        for (int j = 0; j < 16; j++) {
            int row = warp * 16 + j;
            const float4* Wr4 = (const float4*)(Wp + (size_t)row * 256);
            float4 w0 = Wr4[lane], w1 = Wr4[32 + lane];
            float pA = dot8(w0, w1, va0, va1);
            float pB = dot8(w0, w1, vb0, vb1);
#pragma unroll
            for (int o = 16; o > 0; o >>= 1) {
                pA += __shfl_xor_sync(0xffffffffu, pA, o);
                pB += __shfl_xor_sync(0xffffffffu, pB, o);
            }
            if (lane == 0) {
                float bb = bp[row];
                out[(blk * 2 + 0) * 128 + row] = pA + bb;
                out[(blk * 2 + 1) * 128 + row] = pB + bb;
            }
        }
    }
}

// ---------------- host ----------------
extern "C" void kernel_launch(void* const* d_in, const int* in_sizes, int n_in,
                              void* d_out, int out_size) {
    const float* x    = (const float*)d_in[0];
    const int*   ei   = (const int*)d_in[1];
    const int*   batch= (const int*)d_in[2];
    const float* W1l  = (const float*)d_in[3];
    const float* b1l  = (const float*)d_in[4];
    const float* W1r  = (const float*)d_in[5];
    const float* g1   = (const float*)d_in[6];
    const float* be1  = (const float*)d_in[7];
    const float* rm1  = (const float*)d_in[8];
    const float* rv1  = (const float*)d_in[9];
    const float* W2l  = (const float*)d_in[10];
    const float* b2l  = (const float*)d_in[11];
    const float* W2r  = (const float*)d_in[12];
    const float* g2   = (const float*)d_in[13];
    const float* be2  = (const float*)d_in[14];
    const float* rm2  = (const float*)d_in[15];
    const float* rv2  = (const float*)d_in[16];
    const float* Wih  = (const float*)d_in[17];
    const float* Whh  = (const float*)d_in[18];
    const float* bih  = (const float*)d_in[19];
    const float* bhh  = (const float*)d_in[20];
    const float* Wp   = (const float*)d_in[21];
    const float* bp   = (const float*)d_in[22];

    __half *p_yl, *p_yr, *p_h1;
    float *p_h2, *p_s1, *p_t1, *p_s2, *p_t2;
    cudaGetSymbolAddress((void**)&p_yl, g_yl);
    cudaGetSymbolAddress((void**)&p_yr, g_yr);
    cudaGetSymbolAddress((void**)&p_h1, g_h1);
    cudaGetSymbolAddress((void**)&p_h2, g_h2);
    cudaGetSymbolAddress((void**)&p_s1, g_s1);
    cudaGetSymbolAddress((void**)&p_t1, g_t1);
    cudaGetSymbolAddress((void**)&p_s2, g_s2);
    cudaGetSymbolAddress((void**)&p_t2, g_t2);

    // 1: fused prep
    k_prep<<<512, 256>>>(Wih, Whh, bih, bhh, g1, be1, rm1, rv1, b1l,
                         g2, be2, rm2, rv2, b2l, batch);
    // 2-4: CSR build
    k_hist<<<(EE + 255) / 256, 256>>>(ei);
    k_scan<<<1, 256>>>();
    k_fill<<<(EE + 255) / 256, 256>>>(ei);

    dim3 gL((NN + 127) / 128, 2);
    // 5-6: layer 1 (x fp32 in, h1 fp16 out)
    k_gemm_f16<float><<<gL, 256>>>(x, W1l, W1r, p_yl, p_yr);
    k_agg_h<<<(NN * 32 + 255) / 256, 256>>>(p_s1, p_t1, p_h1);
    // 7-8: layer 2 (h1 fp16 in, h2 fp32 out)
    k_gemm_f16<__half><<<gL, 256>>>(p_h1, W2l, W2r, p_yl, p_yr);
    k_agg_f<<<(NN * 32 + 255) / 256, 256>>>(p_s2, p_t2, p_h2);

    // 9: fused set2set (3 steps) + final projection -> d_out
    k_s2s<<<BB / 2, 256>>>(Wp, bp, (float*)d_out);
}

// round 17
// speedup vs baseline: 1.5195x; 1.5195x over previous
#include <cuda_runtime.h>
#include <cuda_fp16.h>
#include <cstdint>

#define NN 40000
#define EE 640000
#define BB 256

// ---------------- scratch (device globals; no allocation) ----------------
__device__ __half g_yl[NN * 128];      // lin_l output (gathered) fp16
__device__ __half g_yr[NN * 128];      // lin_r output fp16
__device__ __half g_h1[NN * 128];      // layer-1 output fp16
__device__ float g_h2[NN * 128];       // layer-2 output fp32 (s2s input)
__device__ float g_inv[NN];
__device__ int   g_dc[2 * NN];         // deg | cursor
__device__ int   g_start[NN + 1];
__device__ int   g_csr[EE];            // src ids sorted by dst
__device__ int   g_seg[BB + 1];
__device__ __half g_Wch[512 * 256];    // fp16 [Wih[:,:128]+Whh | Wih[:,128:]]
__device__ float g_bl[512];            // bih + bhh
__device__ float g_s1[128], g_t1[128], g_s2[128], g_t2[128];

// ---------------- helpers ----------------
__device__ __forceinline__ float sigmoidf_(float x) { return 1.f / (1.f + expf(-x)); }

__device__ __forceinline__ void mma_f16(float c[4], uint32_t a0, uint32_t a1,
                                        uint32_t a2, uint32_t a3,
                                        uint32_t b0, uint32_t b1) {
    asm volatile(
        "mma.sync.aligned.m16n8k16.row.col.f32.f16.f16.f32 "
        "{%0,%1,%2,%3}, {%4,%5,%6,%7}, {%8,%9}, {%0,%1,%2,%3};\n"
        : "+f"(c[0]), "+f"(c[1]), "+f"(c[2]), "+f"(c[3])
        : "r"(a0), "r"(a1), "r"(a2), "r"(a3), "r"(b0), "r"(b1));
}

__device__ __forceinline__ float dot8(float4 w0, float4 w1, float4 v0, float4 v1) {
    return w0.x * v0.x + w0.y * v0.y + w0.z * v0.z + w0.w * v0.w
         + w1.x * v1.x + w1.y * v1.y + w1.z * v1.z + w1.w * v1.w;
}

__device__ __forceinline__ float dot8h(uint4 wq, float4 v0, float4 v1) {
    float2 f0 = __half22float2(*(__half2*)&wq.x);
    float2 f1 = __half22float2(*(__half2*)&wq.y);
    float2 f2 = __half22float2(*(__half2*)&wq.z);
    float2 f3 = __half22float2(*(__half2*)&wq.w);
    return f0.x * v0.x + f0.y * v0.y + f1.x * v0.z + f1.y * v0.w
         + f2.x * v1.x + f2.y * v1.y + f3.x * v1.z + f3.y * v1.w;
}

// smem A-tile loaders: fp32 source (convert) vs fp16 source (raw copy)
__device__ __forceinline__ void load_a4(__half* dst, const float* src) {
    float4 v = *(const float4*)src;
    *(__half2*)dst       = __floats2half2_rn(v.x, v.y);
    *(__half2*)(dst + 2) = __floats2half2_rn(v.z, v.w);
}
__device__ __forceinline__ void load_a4(__half* dst, const __half* src) {
    *(uint2*)dst = *(const uint2*)src;
}

// ---------------- fused prep: pack Wch/bl, fold BN, zero counters, seg bounds ----------------
__global__ void k_prep(const float* __restrict__ Wih, const float* __restrict__ Whh,
                       const float* __restrict__ bih, const float* __restrict__ bhh,
                       const float* __restrict__ g1, const float* __restrict__ be1,
                       const float* __restrict__ rm1, const float* __restrict__ rv1,
                       const float* __restrict__ b1l,
                       const float* __restrict__ g2, const float* __restrict__ be2,
                       const float* __restrict__ rm2, const float* __restrict__ rv2,
                       const float* __restrict__ b2l,
                       const int* __restrict__ batch) {
    int i = blockIdx.x * blockDim.x + threadIdx.x;
    if (i < 512 * 256) {
        int r = i >> 8, k = i & 255;
        float w = Wih[r * 256 + k];
        if (k < 128) w += Whh[r * 128 + k];
        g_Wch[i] = __float2half(w);
    }
    if (i < 512) g_bl[i] = bih[i] + bhh[i];
    if (i < 128) {
        float s = g1[i] * rsqrtf(rv1[i] + 1e-5f);
        g_s1[i] = s; g_t1[i] = be1[i] + (b1l[i] - rm1[i]) * s;
    } else if (i < 256) {
        int j = i - 128;
        float s = g2[j] * rsqrtf(rv2[j] + 1e-5f);
        g_s2[j] = s; g_t2[j] = be2[j] + (b2l[j] - rm2[j]) * s;
    }
    if (i < NN) {
        g_dc[i] = 0; g_dc[NN + i] = 0;
        int b = batch[i];
        int prev = (i == 0) ? -1 : batch[i - 1];
        for (int q = prev + 1; q <= b; q++) g_seg[q] = i;
        if (i == NN - 1)
            for (int q = b + 1; q <= BB; q++) g_seg[q] = NN;
    }
}

// ---------------- CSR build ----------------
__global__ void k_hist(const int* __restrict__ ei) {
    int e = blockIdx.x * blockDim.x + threadIdx.x;
    if (e < EE) atomicAdd(&g_dc[ei[EE + e]], 1);
}

__global__ void k_scan() {  // single block, 256 threads
    __shared__ int part[256];
    int tid = threadIdx.x;
    const int chunk = (NN + 255) / 256;
    int b0 = tid * chunk, b1 = min(b0 + chunk, NN);
    int s = 0;
    for (int i = b0; i < b1; i++) s += g_dc[i];
    part[tid] = s;
    __syncthreads();
    for (int off = 1; off < 256; off <<= 1) {
        int v = (tid >= off) ? part[tid - off] : 0;
        __syncthreads();
        part[tid] += v;
        __syncthreads();
    }
    int base = (tid == 0) ? 0 : part[tid - 1];
    for (int i = b0; i < b1; i++) {
        int d = g_dc[i];
        g_start[i] = base;
        g_inv[i] = 1.f / (float)max(d, 1);
        base += d;
    }
    if (tid == 255) g_start[NN] = base;
}

__global__ void k_fill(const int* __restrict__ ei) {
    int e = blockIdx.x * blockDim.x + threadIdx.x;
    if (e >= EE) return;
    int s = ei[e], d = ei[EE + e];
    int pos = g_start[d] + atomicAdd(&g_dc[NN + d], 1);
    g_csr[pos] = s;
}

// ---------------- fp16 tensor-core GEMM (R15, unchanged) ----------------
template <typename TA>
__global__ __launch_bounds__(256) void k_gemm_f16(
    const TA* __restrict__ A,
    const float* __restrict__ Wl, const float* __restrict__ Wr,
    __half* __restrict__ Yl, __half* __restrict__ Yr) {
    __shared__ __half As[128][40];
    __shared__ __half Bs[128][40];
    const float* W = blockIdx.y ? Wr : Wl;
    __half* Y = blockIdx.y ? Yr : Yl;
    int m0 = blockIdx.x * 128;
    int tid = threadIdx.x;
    int warp = tid >> 5, lane = tid & 31;
    int wm = warp >> 1, wn = warp & 1;
    int gid = lane >> 2, tig = lane & 3;

    float acc[2][8][4];
#pragma unroll
    for (int i = 0; i < 2; i++)
#pragma unroll
        for (int j = 0; j < 8; j++)
#pragma unroll
            for (int q = 0; q < 4; q++) acc[i][j][q] = 0.f;

    int lrow = tid >> 3;
    int lk4 = (tid & 7) * 4;

    for (int kc = 0; kc < 128; kc += 32) {
#pragma unroll
        for (int i = 0; i < 4; i++) {
            int row = lrow + 32 * i;
            int r = m0 + row;
            int rc = min(r, NN - 1);
            load_a4(&As[row][lk4], A + (size_t)rc * 128 + kc + lk4);
            float4 w = *(const float4*)(W + (size_t)row * 128 + kc + lk4);
            *(__half2*)&Bs[row][lk4]     = __floats2half2_rn(w.x, w.y);
            *(__half2*)&Bs[row][lk4 + 2] = __floats2half2_rn(w.z, w.w);
        }
        __syncthreads();
#pragma unroll
        for (int ks = 0; ks < 32; ks += 16) {
            uint32_t a[2][4];
#pragma unroll
            for (int mt = 0; mt < 2; mt++) {
                int mb = wm * 32 + mt * 16;
                a[mt][0] = *(const uint32_t*)&As[mb + gid][ks + tig * 2];
                a[mt][1] = *(const uint32_t*)&As[mb + gid + 8][ks + tig * 2];
                a[mt][2] = *(const uint32_t*)&As[mb + gid][ks + tig * 2 + 8];
                a[mt][3] = *(const uint32_t*)&As[mb + gid + 8][ks + tig * 2 + 8];
            }
#pragma unroll
            for (int nt = 0; nt < 8; nt++) {
                int nb = wn * 64 + nt * 8;
                uint32_t b0 = *(const uint32_t*)&Bs[nb + gid][ks + tig * 2];
                uint32_t b1 = *(const uint32_t*)&Bs[nb + gid][ks + tig * 2 + 8];
                mma_f16(acc[0][nt], a[0][0], a[0][1], a[0][2], a[0][3], b0, b1);
                mma_f16(acc[1][nt], a[1][0], a[1][1], a[1][2], a[1][3], b0, b1);
            }
        }
        __syncthreads();
    }

    int ncol0 = wn * 64;
#pragma unroll
    for (int mt = 0; mt < 2; mt++) {
        int row0 = m0 + wm * 32 + mt * 16 + gid;
        int row1 = row0 + 8;
#pragma unroll
        for (int nt = 0; nt < 8; nt++) {
            int c = ncol0 + nt * 8 + tig * 2;
            if (row0 < NN)
                *(__half2*)(Y + (size_t)row0 * 128 + c) =
                    __floats2half2_rn(acc[mt][nt][0], acc[mt][nt][1]);
            if (row1 < NN)
                *(__half2*)(Y + (size_t)row1 * 128 + c) =
                    __floats2half2_rn(acc[mt][nt][2], acc[mt][nt][3]);
        }
    }
}

// ---------------- CSR aggregation (R15 form: warp per node, uint2/lane, x4 unroll) ----------------
template <int FP16OUT>
__device__ __forceinline__ void agg_body(const float* __restrict__ s,
                                         const float* __restrict__ t,
                                         float* __restrict__ out32,
                                         __half* __restrict__ out16) {
    int gt = blockIdx.x * blockDim.x + threadIdx.x;
    int w = gt >> 5;
    if (w >= NN) return;
    int lane = gt & 31;
    int e0 = g_start[w], e1 = g_start[w + 1];
    float4 acc0 = make_float4(0.f, 0.f, 0.f, 0.f);
    float4 acc1 = make_float4(0.f, 0.f, 0.f, 0.f);
    float4 acc2 = make_float4(0.f, 0.f, 0.f, 0.f);
    float4 acc3 = make_float4(0.f, 0.f, 0.f, 0.f);
    const uint2* Yl2 = (const uint2*)g_yl;
    int e = e0;
    for (; e + 4 <= e1; e += 4) {
        int sa = __ldg(g_csr + e);
        int sb = __ldg(g_csr + e + 1);
        int sc = __ldg(g_csr + e + 2);
        int sd = __ldg(g_csr + e + 3);
        uint2 ua = Yl2[(size_t)sa * 32 + lane];
        uint2 ub = Yl2[(size_t)sb * 32 + lane];
        uint2 uc = Yl2[(size_t)sc * 32 + lane];
        uint2 ud = Yl2[(size_t)sd * 32 + lane];
        float2 a0 = __half22float2(*(__half2*)&ua.x);
        float2 a1 = __half22float2(*(__half2*)&ua.y);
        float2 b0 = __half22float2(*(__half2*)&ub.x);
        float2 b1 = __half22float2(*(__half2*)&ub.y);
        float2 c0 = __half22float2(*(__half2*)&uc.x);
        float2 c1 = __half22float2(*(__half2*)&uc.y);
        float2 d0 = __half22float2(*(__half2*)&ud.x);
        float2 d1 = __half22float2(*(__half2*)&ud.y);
        acc0.x += a0.x; acc0.y += a0.y; acc0.z += a1.x; acc0.w += a1.y;
        acc1.x += b0.x; acc1.y += b0.y; acc1.z += b1.x; acc1.w += b1.y;
        acc2.x += c0.x; acc2.y += c0.y; acc2.z += c1.x; acc2.w += c1.y;
        acc3.x += d0.x; acc3.y += d0.y; acc3.z += d1.x; acc3.w += d1.y;
    }
    for (; e < e1; e++) {
        int sa = __ldg(g_csr + e);
        uint2 ua = Yl2[(size_t)sa * 32 + lane];
        float2 a0 = __half22float2(*(__half2*)&ua.x);
        float2 a1 = __half22float2(*(__half2*)&ua.y);
        acc0.x += a0.x; acc0.y += a0.y; acc0.z += a1.x; acc0.w += a1.y;
    }
    acc0.x += acc1.x + acc2.x + acc3.x;
    acc0.y += acc1.y + acc2.y + acc3.y;
    acc0.z += acc1.z + acc2.z + acc3.z;
    acc0.w += acc1.w + acc2.w + acc3.w;
    float iv = g_inv[w];
    uint2 ur = ((const uint2*)g_yr)[(size_t)w * 32 + lane];
    float2 r0 = __half22float2(*(__half2*)&ur.x);
    float2 r1 = __half22float2(*(__half2*)&ur.y);
    float4 sv = ((const float4*)s)[lane];
    float4 tv = ((const float4*)t)[lane];
    float4 o;
    o.x = fmaxf(fmaf(fmaf(acc0.x, iv, r0.x), sv.x, tv.x), 0.f);
    o.y = fmaxf(fmaf(fmaf(acc0.y, iv, r0.y), sv.y, tv.y), 0.f);
    o.z = fmaxf(fmaf(fmaf(acc0.z, iv, r1.x), sv.z, tv.z), 0.f);
    o.w = fmaxf(fmaf(fmaf(acc0.w, iv, r1.y), sv.w, tv.w), 0.f);
    if (FP16OUT) {
        uint2 pk;
        *(__half2*)&pk.x = __floats2half2_rn(o.x, o.y);
        *(__half2*)&pk.y = __floats2half2_rn(o.z, o.w);
        ((uint2*)out16)[(size_t)w * 32 + lane] = pk;
    } else {
        ((float4*)out32)[(size_t)w * 32 + lane] = o;
    }
}

__global__ void k_agg_h(const float* __restrict__ s, const float* __restrict__ t,
                        __half* __restrict__ out) {
    agg_body<1>(s, t, nullptr, out);
}
__global__ void k_agg_f(const float* __restrict__ s, const float* __restrict__ t,
                        float* __restrict__ out) {
    agg_body<0>(s, t, out, nullptr);
}

// ---------------- fused set2set (3 steps) + final projection ----------------
// 128 blocks x 256 threads; 2 graphs per block, 4 warps per graph.
// Gate loop: 2 rows/iteration -> 4 interleaved shfl chains (ILP on latency-bound loop).
__global__ __launch_bounds__(256) void k_s2s(const float* __restrict__ Wp,
                                             const float* __restrict__ bp,
                                             float* __restrict__ out) {
    int blk = blockIdx.x;
    int tid = threadIdx.x;
    int warp = tid >> 5, lane = tid & 31;
    int gr = warp >> 2;
    int wl = warp & 3;
    int g = blk * 2 + gr;

    __shared__ float sh_v[2][256];
    __shared__ float sh_q[2][128];
    __shared__ float sh_c[2][128];
    __shared__ float sh_gates[2][512];
    __shared__ float sh_r[2][4][128];
    __shared__ float sh_s[2][8];

    if (tid < 128) { sh_c[0][tid] = 0.f; sh_c[1][tid] = 0.f; }
    __syncthreads();

    int s0 = g_seg[g], s1 = g_seg[g + 1];
    const float4* H4 = (const float4*)g_h2;

    for (int step = 0; step < 3; step++) {
        // ---- gates ----
        if (step == 0) {
            float b0 = g_bl[tid], b1 = g_bl[256 + tid];
            sh_gates[0][tid] = b0; sh_gates[0][256 + tid] = b1;
            sh_gates[1][tid] = b0; sh_gates[1][256 + tid] = b1;
        } else {
            const float4* VA = (const float4*)sh_v[0];
            const float4* VB = (const float4*)sh_v[1];
            float4 va0 = VA[2 * lane], va1 = VA[2 * lane + 1];
            float4 vb0 = VB[2 * lane], vb1 = VB[2 * lane + 1];
#pragma unroll 2
            for (int j = 0; j < 32; j++) {
                int r0 = warp * 64 + j;
                int r1 = r0 + 32;
                uint4 wq0 = *(const uint4*)(g_Wch + (size_t)r0 * 256 + lane * 8);
                uint4 wq1 = *(const uint4*)(g_Wch + (size_t)r1 * 256 + lane * 8);
                float p0A = dot8h(wq0, va0, va1);
                float p0B = dot8h(wq0, vb0, vb1);
                float p1A = dot8h(wq1, va0, va1);
                float p1B = dot8h(wq1, vb0, vb1);
#pragma unroll
                for (int o = 16; o > 0; o >>= 1) {
                    p0A += __shfl_xor_sync(0xffffffffu, p0A, o);
                    p0B += __shfl_xor_sync(0xffffffffu, p0B, o);
                    p1A += __shfl_xor_sync(0xffffffffu, p1A, o);
                    p1B += __shfl_xor_sync(0xffffffffu, p1B, o);
                }
                if (lane == 0) {
                    float bb0 = g_bl[r0], bb1 = g_bl[r1];
                    sh_gates[0][r0] = p0A + bb0;
                    sh_gates[1][r0] = p0B + bb0;
                    sh_gates[0][r1] = p1A + bb1;
                    sh_gates[1][r1] = p1B + bb1;
                }
            }
        }
        __syncthreads();

        // ---- LSTM cell ----
        {
            int gg = tid >> 7, d = tid & 127;
            float ig = sh_gates[gg][d], fg = sh_gates[gg][128 + d];
            float gv = sh_gates[gg][256 + d], og = sh_gates[gg][384 + d];
            float c0 = sh_c[gg][d];
            float cn = sigmoidf_(fg) * c0 + sigmoidf_(ig) * tanhf(gv);
            float hn = sigmoidf_(og) * tanhf(cn);
            sh_c[gg][d] = cn;
            sh_q[gg][d] = hn;
        }
        __syncthreads();

        // ---- attention pass 1: segment max ----
        float4 qv = ((const float4*)sh_q[gr])[lane];
        float wmax = -3.402823466e38f;
        for (int n = s0 + wl; n < s1; n += 4) {
            float4 hv = H4[(size_t)n * 32 + lane];
            float p = hv.x * qv.x + hv.y * qv.y + hv.z * qv.z + hv.w * qv.w;
#pragma unroll
            for (int o = 16; o > 0; o >>= 1) p += __shfl_xor_sync(0xffffffffu, p, o);
            wmax = fmaxf(wmax, p);
        }
        if (lane == 0) sh_s[gr][wl] = wmax;
        __syncthreads();
        float emax = fmaxf(fmaxf(sh_s[gr][0], sh_s[gr][1]),
                           fmaxf(sh_s[gr][2], sh_s[gr][3]));

        // ---- attention pass 2: exp-sum + weighted feature sum ----
        float asum = 0.f;
        float4 racc = make_float4(0.f, 0.f, 0.f, 0.f);
        for (int n = s0 + wl; n < s1; n += 4) {
            float4 hv = H4[(size_t)n * 32 + lane];
            float p = hv.x * qv.x + hv.y * qv.y + hv.z * qv.z + hv.w * qv.w;
#pragma unroll
            for (int o = 16; o > 0; o >>= 1) p += __shfl_xor_sync(0xffffffffu, p, o);
            float a = expf(p - emax);
            asum += a;
            racc.x += a * hv.x; racc.y += a * hv.y; racc.z += a * hv.z; racc.w += a * hv.w;
        }
        ((float4*)sh_r[gr][wl])[lane] = racc;
        if (lane == 0) sh_s[gr][4 + wl] = asum;
        __syncthreads();

        // ---- combine: q_star = [q | r] ----
        {
            int gg = tid >> 7, d = tid & 127;
            float den = sh_s[gg][4] + sh_s[gg][5] + sh_s[gg][6] + sh_s[gg][7];
            float rsum = sh_r[gg][0][d] + sh_r[gg][1][d] + sh_r[gg][2][d] + sh_r[gg][3][d];
            float r = (den > 0.f) ? rsum / den : 0.f;
            sh_v[gg][d] = sh_q[gg][d];
            sh_v[gg][128 + d] = r;
        }
        __syncthreads();
    }

    // ---- final projection: 2 rows/iteration, 4 interleaved chains ----
    {
        const float4* VA = (const float4*)sh_v[0];
        const float4* VB = (const float4*)sh_v[1];
        float4 va0 = VA[lane], va1 = VA[32 + lane];
        float4 vb0 = VB[lane], vb1 = VB[32 + lane];
#pragma unroll 2
        for (int j = 0; j < 8; j++) {
            int row0 = warp * 16 + j;
            int row1 = row0 + 8;
            const float4* W0 = (const float4*)(Wp + (size_t)row0 * 256);
            const float4* W1 = (const float4*)(Wp + (size_t)row1 * 256);
            float4 w00 = W0[lane], w01 = W0[32 + lane];
            float4 w10 = W1[lane], w11 = W1[32 + lane];
            float p0A = dot8(w00, w01, va0, va1);
            float p0B = dot8(w00, w01, vb0, vb1);
            float p1A = dot8(w10, w11, va0, va1);
            float p1B = dot8(w10, w11, vb0, vb1);
#pragma unroll
            for (int o = 16; o > 0; o >>= 1) {
                p0A += __shfl_xor_sync(0xffffffffu, p0A, o);
                p0B += __shfl_xor_sync(0xffffffffu, p0B, o);
                p1A += __shfl_xor_sync(0xffffffffu, p1A, o);
                p1B += __shfl_xor_sync(0xffffffffu, p1B, o);
            }
            if (lane == 0) {
                float bb0 = bp[row0], bb1 = bp[row1];
                out[(blk * 2 + 0) * 128 + row0] = p0A + bb0;
                out[(blk * 2 + 1) * 128 + row0] = p0B + bb0;
                out[(blk * 2 + 0) * 128 + row1] = p1A + bb1;
                out[(blk * 2 + 1) * 128 + row1] = p1B + bb1;
            }
        }
    }
}

// ---------------- host ----------------
extern "C" void kernel_launch(void* const* d_in, const int* in_sizes, int n_in,
                              void* d_out, int out_size) {
    const float* x    = (const float*)d_in[0];
    const int*   ei   = (const int*)d_in[1];
    const int*   batch= (const int*)d_in[2];
    const float* W1l  = (const float*)d_in[3];
    const float* b1l  = (const float*)d_in[4];
    const float* W1r  = (const float*)d_in[5];
    const float* g1   = (const float*)d_in[6];
    const float* be1  = (const float*)d_in[7];
    const float* rm1  = (const float*)d_in[8];
    const float* rv1  = (const float*)d_in[9];
    const float* W2l  = (const float*)d_in[10];
    const float* b2l  = (const float*)d_in[11];
    const float* W2r  = (const float*)d_in[12];
    const float* g2   = (const float*)d_in[13];
    const float* be2  = (const float*)d_in[14];
    const float* rm2  = (const float*)d_in[15];
    const float* rv2  = (const float*)d_in[16];
    const float* Wih  = (const float*)d_in[17];
    const float* Whh  = (const float*)d_in[18];
    const float* bih  = (const float*)d_in[19];
    const float* bhh  = (const float*)d_in[20];
    const float* Wp   = (const float*)d_in[21];
    const float* bp   = (const float*)d_in[22];

    __half *p_yl, *p_yr, *p_h1;
    float *p_h2, *p_s1, *p_t1, *p_s2, *p_t2;
    cudaGetSymbolAddress((void**)&p_yl, g_yl);
    cudaGetSymbolAddress((void**)&p_yr, g_yr);
    cudaGetSymbolAddress((void**)&p_h1, g_h1);
    cudaGetSymbolAddress((void**)&p_h2, g_h2);
    cudaGetSymbolAddress((void**)&p_s1, g_s1);
    cudaGetSymbolAddress((void**)&p_t1, g_t1);
    cudaGetSymbolAddress((void**)&p_s2, g_s2);
    cudaGetSymbolAddress((void**)&p_t2, g_t2);

    // 1: fused prep
    k_prep<<<512, 256>>>(Wih, Whh, bih, bhh, g1, be1, rm1, rv1, b1l,
                         g2, be2, rm2, rv2, b2l, batch);
    // 2-4: CSR build
    k_hist<<<(EE + 255) / 256, 256>>>(ei);
    k_scan<<<1, 256>>>();
    k_fill<<<(EE + 255) / 256, 256>>>(ei);

    dim3 gL((NN + 127) / 128, 2);
    // 5-6: layer 1 (x fp32 in, h1 fp16 out)
    k_gemm_f16<float><<<gL, 256>>>(x, W1l, W1r, p_yl, p_yr);
    k_agg_h<<<(NN * 32 + 255) / 256, 256>>>(p_s1, p_t1, p_h1);
    // 7-8: layer 2 (h1 fp16 in, h2 fp32 out)
    k_gemm_f16<__half><<<gL, 256>>>(p_h1, W2l, W2r, p_yl, p_yr);
    k_agg_f<<<(NN * 32 + 255) / 256, 256>>>(p_s2, p_t2, p_h2);

    // 9: fused set2set (3 steps) + final projection -> d_out
    k_s2s<<<BB / 2, 256>>>(Wp, bp, (float*)d_out);
}